// round 1
// baseline (speedup 1.0000x reference)
#include <cuda_runtime.h>
#include <cuda_bf16.h>

#define FM        64
#define MAXV      100000
#define MAXC      50000
#define MAXNNZ    2000000
#define OUTB      16

// ---------------- scratch (static device globals; no runtime alloc) --------
__device__ float g_vars[MAXV * FM];     // variables   [V,64]
__device__ float g_cons[MAXC * FM];     // constraints [C,64]
__device__ float g_v2c [MAXC * FM];
__device__ float g_c2v [MAXV * FM];

__device__ int   g_cntC[MAXC];
__device__ int   g_cntV[MAXV];
__device__ int   g_offC[MAXC + 1];
__device__ int   g_offV[MAXV + 1];
__device__ int   g_curC[MAXC];
__device__ int   g_curV[MAXV];

__device__ int   g_cscRow[MAXNNZ];
__device__ float g_cscVal[MAXNNZ];
__device__ int   g_csrCol[MAXNNZ];
__device__ float g_csrVal[MAXNNZ];

// ---------------- CSR/CSC build --------------------------------------------
__global__ void zero_counts_kernel(int nC, int nV) {
    int i = blockIdx.x * blockDim.x + threadIdx.x;
    if (i < nC) g_cntC[i] = 0;
    if (i < nV) g_cntV[i] = 0;
}

__global__ void hist_kernel(const int* __restrict__ row, const int* __restrict__ col, int nnz) {
    int e = blockIdx.x * blockDim.x + threadIdx.x;
    if (e < nnz) {
        atomicAdd(&g_cntC[col[e]], 1);
        atomicAdd(&g_cntV[row[e]], 1);
    }
}

// block 0 scans C-side, block 1 scans V-side (1024 threads each)
__global__ void scan_kernel(int nC, int nV) {
    const int* cnt; int* off; int* cur; int n;
    if (blockIdx.x == 0) { cnt = g_cntC; off = g_offC; cur = g_curC; n = nC; }
    else                 { cnt = g_cntV; off = g_offV; cur = g_curV; n = nV; }

    __shared__ int part[1024];
    int t = threadIdx.x;
    int chunk = (n + 1023) / 1024;
    int beg = t * chunk;
    int end = min(n, beg + chunk);

    int s = 0;
    for (int i = beg; i < end; i++) s += cnt[i];
    part[t] = s;
    __syncthreads();
    for (int d = 1; d < 1024; d <<= 1) {
        int v = (t >= d) ? part[t - d] : 0;
        __syncthreads();
        part[t] += v;
        __syncthreads();
    }
    int run = (t == 0) ? 0 : part[t - 1];
    for (int i = beg; i < end; i++) {
        off[i] = run; cur[i] = run;
        run += cnt[i];
    }
    if (t == 1023) off[n] = part[1023];
}

__global__ void fill_kernel(const int* __restrict__ row, const int* __restrict__ col,
                            const float* __restrict__ av, int nnz) {
    int e = blockIdx.x * blockDim.x + threadIdx.x;
    if (e < nnz) {
        int r = row[e], c = col[e];
        float v = fabsf(av[e]);
        int p = atomicAdd(&g_curC[c], 1);
        g_cscRow[p] = r; g_cscVal[p] = v;
        int q = atomicAdd(&g_curV[r], 1);
        g_csrCol[q] = c; g_csrVal[q] = v;
    }
}

__global__ void init_vars_kernel(int n) {
    int i = blockIdx.x * blockDim.x + threadIdx.x;
    if (i < n) g_vars[i] = 1.0f;
}

// ---------------- segment gather-reduce (warp per segment) -----------------
__global__ void seg_gather_kernel(const int* __restrict__ offs,
                                  const int* __restrict__ idxArr,
                                  const float* __restrict__ valArr,
                                  const float* __restrict__ srcF,
                                  float* __restrict__ dstF, int nseg) {
    int warp = threadIdx.x >> 5;
    int lane = threadIdx.x & 31;
    int seg  = blockIdx.x * (blockDim.x >> 5) + warp;
    if (seg >= nseg) return;

    int s = offs[seg], e = offs[seg + 1];
    float ax = 0.f, ay = 0.f;
    int p = s;
    for (; p + 4 <= e; p += 4) {
        int   i0 = idxArr[p + 0], i1 = idxArr[p + 1], i2 = idxArr[p + 2], i3 = idxArr[p + 3];
        float v0 = valArr[p + 0], v1 = valArr[p + 1], v2 = valArr[p + 2], v3 = valArr[p + 3];
        float2 f0 = *(const float2*)&srcF[(size_t)i0 * FM + 2 * lane];
        float2 f1 = *(const float2*)&srcF[(size_t)i1 * FM + 2 * lane];
        float2 f2 = *(const float2*)&srcF[(size_t)i2 * FM + 2 * lane];
        float2 f3 = *(const float2*)&srcF[(size_t)i3 * FM + 2 * lane];
        ax += v0 * f0.x; ay += v0 * f0.y;
        ax += v1 * f1.x; ay += v1 * f1.y;
        ax += v2 * f2.x; ay += v2 * f2.y;
        ax += v3 * f3.x; ay += v3 * f3.y;
    }
    for (; p < e; p++) {
        int   i0 = idxArr[p];
        float v0 = valArr[p];
        float2 f0 = *(const float2*)&srcF[(size_t)i0 * FM + 2 * lane];
        ax += v0 * f0.x; ay += v0 * f0.y;
    }
    *(float2*)&dstF[(size_t)seg * FM + 2 * lane] = make_float2(ax, ay);
}

// ---------------- MLP layer-2 (128 -> 64), shared by prep + main MLPs ------
// sb holds 4 rows x 128 hidden activations; lane handles out cols {2l, 2l+1}
__device__ __forceinline__ void mlp_layer2_64(const float* sb,
                                              const float* __restrict__ W2,
                                              const float* __restrict__ b2,
                                              float* __restrict__ outp,
                                              int row0, int rows, int lane) {
    float2 acc[4];
#pragma unroll
    for (int r = 0; r < 4; r++) acc[r] = make_float2(0.f, 0.f);

    for (int k = 0; k < 128; k += 4) {
        float4 hv[4];
#pragma unroll
        for (int r = 0; r < 4; r++) hv[r] = *(const float4*)&sb[r * 128 + k];
#pragma unroll
        for (int kk = 0; kk < 4; kk++) {
            float2 w = *(const float2*)&W2[(k + kk) * 64 + 2 * lane];
#pragma unroll
            for (int r = 0; r < 4; r++) {
                float hk = ((const float*)&hv[r])[kk];
                acc[r].x += hk * w.x;
                acc[r].y += hk * w.y;
            }
        }
    }
    float2 bb = *(const float2*)&b2[2 * lane];
#pragma unroll
    for (int r = 0; r < 4; r++) {
        if (row0 + r < rows) {
            float2 o = make_float2(acc[r].x + bb.x, acc[r].y + bb.y);
            *(float2*)&outp[(size_t)(row0 + r) * 64 + 2 * lane] = o;
        }
    }
}

// ---------------- main MLP: concat(inA[64], inB[64]) -> 128(relu) -> 64 ----
// warp processes 4 rows; block = 8 warps = 32 rows
__global__ void mlp128_kernel(const float* __restrict__ inA,
                              const float* __restrict__ inB,
                              float* __restrict__ outp,
                              const float* __restrict__ W1, const float* __restrict__ b1,
                              const float* __restrict__ W2, const float* __restrict__ b2,
                              int rows) {
    __shared__ float sbuf[8][512];
    int warp = threadIdx.x >> 5;
    int lane = threadIdx.x & 31;
    int row0 = (blockIdx.x * 8 + warp) * 4;
    if (row0 >= rows) return;
    float* sb = sbuf[warp];

    // load concat input: 128 floats/row; lane loads float4 at k=4*lane
#pragma unroll
    for (int r = 0; r < 4; r++) {
        int row = min(row0 + r, rows - 1);
        float4 v;
        if (lane < 16) v = *(const float4*)&inA[(size_t)row * 64 + lane * 4];
        else           v = *(const float4*)&inB[(size_t)row * 64 + (lane - 16) * 4];
        *(float4*)&sb[r * 128 + lane * 4] = v;
    }
    __syncwarp();

    // layer 1: lane computes hidden j = 4*lane + t, 4 rows
    float4 acc[4];
#pragma unroll
    for (int r = 0; r < 4; r++) acc[r] = make_float4(0.f, 0.f, 0.f, 0.f);

    for (int k = 0; k < 128; k += 4) {
        float4 xv[4];
#pragma unroll
        for (int r = 0; r < 4; r++) xv[r] = *(const float4*)&sb[r * 128 + k];
#pragma unroll
        for (int kk = 0; kk < 4; kk++) {
            float4 w = *(const float4*)&W1[(k + kk) * 128 + 4 * lane];
#pragma unroll
            for (int r = 0; r < 4; r++) {
                float xk = ((const float*)&xv[r])[kk];
                acc[r].x += xk * w.x;
                acc[r].y += xk * w.y;
                acc[r].z += xk * w.z;
                acc[r].w += xk * w.w;
            }
        }
    }
    float4 bb = *(const float4*)&b1[4 * lane];
    __syncwarp();
#pragma unroll
    for (int r = 0; r < 4; r++) {
        float4 h;
        h.x = fmaxf(acc[r].x + bb.x, 0.f);
        h.y = fmaxf(acc[r].y + bb.y, 0.f);
        h.z = fmaxf(acc[r].z + bb.z, 0.f);
        h.w = fmaxf(acc[r].w + bb.w, 0.f);
        *(float4*)&sb[r * 128 + 4 * lane] = h;
    }
    __syncwarp();

    mlp_layer2_64(sb, W2, b2, outp, row0, rows, lane);
}

// ---------------- prepare_cond: scalar -> 128(relu) -> 64 ------------------
__global__ void prep_kernel(const float* __restrict__ cond,
                            const float* __restrict__ w1, const float* __restrict__ b1,
                            const float* __restrict__ w2, const float* __restrict__ b2,
                            int rows) {
    __shared__ float sbuf[8][512];
    int warp = threadIdx.x >> 5;
    int lane = threadIdx.x & 31;
    int row0 = (blockIdx.x * 8 + warp) * 4;
    if (row0 >= rows) return;
    float* sb = sbuf[warp];

    float4 w = *(const float4*)&w1[4 * lane];
    float4 b = *(const float4*)&b1[4 * lane];
#pragma unroll
    for (int r = 0; r < 4; r++) {
        int row = min(row0 + r, rows - 1);
        float c = cond[row];
        float4 h;
        h.x = fmaxf(c * w.x + b.x, 0.f);
        h.y = fmaxf(c * w.y + b.y, 0.f);
        h.z = fmaxf(c * w.z + b.z, 0.f);
        h.w = fmaxf(c * w.w + b.w, 0.f);
        *(float4*)&sb[r * 128 + 4 * lane] = h;
    }
    __syncwarp();
    mlp_layer2_64(sb, w2, b2, g_cons, row0, rows, lane);
}

// ---------------- output: 64 -> 128(relu) -> 16 + sigmoid ------------------
__global__ void out_kernel(const float* __restrict__ W1, const float* __restrict__ b1,
                           const float* __restrict__ W2, const float* __restrict__ b2,
                           float* __restrict__ outp, int rows) {
    __shared__ float sbuf[8][512];
    int warp = threadIdx.x >> 5;
    int lane = threadIdx.x & 31;
    int row0 = (blockIdx.x * 8 + warp) * 4;
    if (row0 >= rows) return;
    float* sb = sbuf[warp];

    // load x: 64 floats/row (float2 per lane)
#pragma unroll
    for (int r = 0; r < 4; r++) {
        int row = min(row0 + r, rows - 1);
        float2 v = *(const float2*)&g_vars[(size_t)row * 64 + 2 * lane];
        *(float2*)&sb[r * 128 + 2 * lane] = v;
    }
    __syncwarp();

    // layer 1: hidden j = 4*lane + t
    float4 acc[4];
#pragma unroll
    for (int r = 0; r < 4; r++) acc[r] = make_float4(0.f, 0.f, 0.f, 0.f);
    for (int k = 0; k < 64; k += 4) {
        float4 xv[4];
#pragma unroll
        for (int r = 0; r < 4; r++) xv[r] = *(const float4*)&sb[r * 128 + k];
#pragma unroll
        for (int kk = 0; kk < 4; kk++) {
            float4 w = *(const float4*)&W1[(k + kk) * 128 + 4 * lane];
#pragma unroll
            for (int r = 0; r < 4; r++) {
                float xk = ((const float*)&xv[r])[kk];
                acc[r].x += xk * w.x;
                acc[r].y += xk * w.y;
                acc[r].z += xk * w.z;
                acc[r].w += xk * w.w;
            }
        }
    }
    float4 bb = *(const float4*)&b1[4 * lane];
    __syncwarp();
#pragma unroll
    for (int r = 0; r < 4; r++) {
        float4 h;
        h.x = fmaxf(acc[r].x + bb.x, 0.f);
        h.y = fmaxf(acc[r].y + bb.y, 0.f);
        h.z = fmaxf(acc[r].z + bb.z, 0.f);
        h.w = fmaxf(acc[r].w + bb.w, 0.f);
        *(float4*)&sb[r * 128 + 4 * lane] = h;
    }
    __syncwarp();

    // layer 2: 16 outputs; lanes split: half = lane>>4 handles rows {half, half+2}
    int j = lane & 15;
    int half = lane >> 4;
    float a0 = 0.f, a1 = 0.f;
#pragma unroll 4
    for (int k = 0; k < 128; k++) {
        float w = W2[k * 16 + j];
        a0 += sb[half * 128 + k] * w;
        a1 += sb[(half + 2) * 128 + k] * w;
    }
    float bv = b2[j];
    {
        int r = half;
        if (row0 + r < rows) {
            float z = a0 + bv;
            outp[(size_t)(row0 + r) * OUTB + j] = 1.f / (1.f + __expf(-z));
        }
        r = half + 2;
        if (row0 + r < rows) {
            float z = a1 + bv;
            outp[(size_t)(row0 + r) * OUTB + j] = 1.f / (1.f + __expf(-z));
        }
    }
}

// ---------------- launch ----------------------------------------------------
extern "C" void kernel_launch(void* const* d_in, const int* in_sizes, int n_in,
                              void* d_out, int out_size) {
    const int*   row  = (const int*)  d_in[0];
    const int*   col  = (const int*)  d_in[1];
    const float* adj  = (const float*)d_in[2];
    const float* cond = (const float*)d_in[3];

    int nnz = in_sizes[0];
    int C   = in_sizes[3];
    int V   = out_size / OUTB;
    if (nnz > MAXNNZ) nnz = MAXNNZ;
    if (C > MAXC) C = MAXC;
    if (V > MAXV) V = MAXV;

    int w = 4;
    if (n_in >= 22 && in_sizes[4] == 1 && in_sizes[5] == 1) w = 6;  // skip scalar var/const counts
    const float* pc_w1 = (const float*)d_in[w + 0];
    const float* pc_b1 = (const float*)d_in[w + 1];
    const float* pc_w2 = (const float*)d_in[w + 2];
    const float* pc_b2 = (const float*)d_in[w + 3];
    const float* cu_w1 = (const float*)d_in[w + 4];
    const float* cu_b1 = (const float*)d_in[w + 5];
    const float* cu_w2 = (const float*)d_in[w + 6];
    const float* cu_b2 = (const float*)d_in[w + 7];
    const float* vu_w1 = (const float*)d_in[w + 8];
    const float* vu_b1 = (const float*)d_in[w + 9];
    const float* vu_w2 = (const float*)d_in[w + 10];
    const float* vu_b2 = (const float*)d_in[w + 11];
    const float* o_w1  = (const float*)d_in[w + 12];
    const float* o_b1  = (const float*)d_in[w + 13];
    const float* o_w2  = (const float*)d_in[w + 14];
    const float* o_b2  = (const float*)d_in[w + 15];

    // resolve device-global scratch addresses (no allocation)
    float *p_vars, *p_cons, *p_v2c, *p_c2v, *p_cscVal, *p_csrVal;
    int   *p_offC, *p_offV, *p_cscRow, *p_csrCol;
    cudaGetSymbolAddress((void**)&p_vars,   g_vars);
    cudaGetSymbolAddress((void**)&p_cons,   g_cons);
    cudaGetSymbolAddress((void**)&p_v2c,    g_v2c);
    cudaGetSymbolAddress((void**)&p_c2v,    g_c2v);
    cudaGetSymbolAddress((void**)&p_offC,   g_offC);
    cudaGetSymbolAddress((void**)&p_offV,   g_offV);
    cudaGetSymbolAddress((void**)&p_cscRow, g_cscRow);
    cudaGetSymbolAddress((void**)&p_cscVal, g_cscVal);
    cudaGetSymbolAddress((void**)&p_csrCol, g_csrCol);
    cudaGetSymbolAddress((void**)&p_csrVal, g_csrVal);

    int maxCV = (C > V) ? C : V;

    zero_counts_kernel<<<(maxCV + 255) / 256, 256>>>(C, V);
    hist_kernel<<<(nnz + 255) / 256, 256>>>(row, col, nnz);
    scan_kernel<<<2, 1024>>>(C, V);
    fill_kernel<<<(nnz + 255) / 256, 256>>>(row, col, adj, nnz);
    init_vars_kernel<<<(V * FM + 255) / 256, 256>>>(V * FM);
    prep_kernel<<<(C + 31) / 32, 256>>>(cond, pc_w1, pc_b1, pc_w2, pc_b2, C);

    for (int it = 0; it < 3; it++) {
        // var -> const
        seg_gather_kernel<<<(C + 7) / 8, 256>>>(p_offC, p_cscRow, p_cscVal, p_vars, p_v2c, C);
        mlp128_kernel<<<(C + 31) / 32, 256>>>(p_cons, p_v2c, p_cons,
                                              cu_w1, cu_b1, cu_w2, cu_b2, C);
        // const -> var
        seg_gather_kernel<<<(V + 7) / 8, 256>>>(p_offV, p_csrCol, p_csrVal, p_cons, p_c2v, V);
        mlp128_kernel<<<(V + 31) / 32, 256>>>(p_vars, p_c2v, p_vars,
                                              vu_w1, vu_b1, vu_w2, vu_b2, V);
    }

    out_kernel<<<(V + 31) / 32, 256>>>(o_w1, o_b1, o_w2, o_b2, (float*)d_out, V);
}